// round 13
// baseline (speedup 1.0000x reference)
#include <cuda_runtime.h>
#include <cstdint>
#include <math.h>
#include <float.h>

// Problem constants
#define BK  8
#define CK  32
#define KK  512
#define ROWS 8
#define TPB 512

// Decision bitmasks: bit (j&31) of g_mask[((b*KK+i)<<4) + (j>>5)]  (256 KB)
__device__ uint32_t g_mask[BK * KK * (KK / 32)];

// ---------------------------------------------------------------------------
// JAX threefry2x32, key = (0, 42).  Random123 Threefry-2x32-20.
// Adds (round + key injection) issued as IMAD via opaque `one` (fma pipe);
// rotations single SHF via __funnelshift_l; xors LOP3. 3 ops per round.
// ---------------------------------------------------------------------------
#define MAD(dst, addend) \
    asm("mad.lo.s32 %0, %1, %2, %0;" : "+r"(dst) : "r"(addend), "r"(one))
#define MADC(dst, cst) { uint32_t k_ = (cst); MAD(dst, k_); }
#define TF_R(r) { MAD(x0, x1); x1 = __funnelshift_l(x1, x1, (r)); x1 ^= x0; }

__device__ __forceinline__ uint32_t jax_bits(uint32_t e, uint32_t one) {
    uint32_t x0 = 0u, x1 = e;
    const uint32_t ks1 = 42u;
    const uint32_t ks2 = 0x1BD11BDAu ^ 42u;
    /* x0 += 0 */  MADC(x1, ks1);
    TF_R(13) TF_R(15) TF_R(26) TF_R(6)
    MADC(x0, ks1); MADC(x1, ks2 + 1u);
    TF_R(17) TF_R(29) TF_R(16) TF_R(24)
    MADC(x0, ks2); MADC(x1, 2u);
    TF_R(13) TF_R(15) TF_R(26) TF_R(6)
    /* x0 += 0 */  MADC(x1, ks1 + 3u);
    TF_R(17) TF_R(29) TF_R(16) TF_R(24)
    MADC(x0, ks1); MADC(x1, ks2 + 4u);
    TF_R(13) TF_R(15) TF_R(26) TF_R(6)
    MADC(x0, ks2); MADC(x1, 5u);
    return x0 ^ x1;
}

// jax.random.uniform bit->float, minval=1e-10, maxval=1.0 (f32).
// f in [0,1) so max(1e-10, f+1e-10) == f+1e-10 exactly.
__device__ __forceinline__ float jax_uniform(uint32_t bits) {
    float f = __uint_as_float((bits >> 9) | 0x3f800000u) - 1.0f;
    return f + 1e-10f;
}

// ---------------------------------------------------------------------------
// Fused kernel. Block = (8-row i-tile, batch b), thread = column j.
// Phase A interleaves the fma-pipe dot product with the alu-pipe threefry in
// the SAME loop iteration, so both pipes are busy concurrently; the gumbel
// ratio t = L1/L0 is parked in smem. Decisions leave as ballot bitmasks.
// ---------------------------------------------------------------------------
__global__ void __launch_bounds__(TPB, 2)
fused_kernel(const float* __restrict__ amp,
             const float* __restrict__ ph,
             const float* __restrict__ Amat,
             const float* __restrict__ wamp_p,
             const float* __restrict__ wph_p,
             uint32_t one) {
    __shared__ float sQi[ROWS][CK];      // row vectors q_i
    __shared__ float sSi[ROWS];          // ||q_i||^2
    __shared__ float sRed[16][ROWS];     // per-warp row minima
    __shared__ float sA[ROWS];           // 0.99 * Dmin per row
    __shared__ float sT[ROWS][KK];       // gumbel ratio L1/L0 (16 KB)

    const int b    = blockIdx.y;
    const int j    = threadIdx.x;
    const int wid  = j >> 5;
    const int lane = j & 31;
    const int i0   = blockIdx.x * ROWS;

    const float wa = wamp_p[0];
    const float wp = wph_p[0];

    const float* ab = amp + (size_t)b * CK * KK;
    const float* pb = ph  + (size_t)b * CK * KK;

    // Per-thread column cache q_j[c] and its sum of squares
    float qj[CK];
    float Sj = 0.0f;
#pragma unroll
    for (int c = 0; c < CK; c++) {
        float v = wa * ab[c * KK + j] + wp * pb[c * KK + j];
        qj[c] = v;
        Sj = fmaf(v, v, Sj);
    }

    // Warps 0..7 load the 8 row vectors (lane = channel) + row SSQ
    if (wid < ROWS) {
        const int i = i0 + wid;
        float v = wa * ab[lane * KK + i] + wp * pb[lane * KK + i];
        sQi[wid][lane] = v;
        float s = v * v;
#pragma unroll
        for (int o = 16; o; o >>= 1)
            s += __shfl_xor_sync(0xffffffffu, s, o);
        if (lane == 0) sSi[wid] = s;
    }

    const float dj   = Amat[(size_t)j * KK + j];
    const float djsq = dj * dj;
    __syncthreads();

    // Phase A: per row r, dist dot product (fma pipe) interleaved with the
    // two threefry calls (alu pipe). unroll 1 keeps registers under the
    // 2-CTA/SM cap; within one iteration there are 4 independent chains.
    float D[ROWS];
#pragma unroll 1
    for (int r = 0; r < ROWS; r++) {
        const int i = i0 + r;

        float dot0 = 0.0f, dot1 = 0.0f;
        const float2* q2 = (const float2*)sQi[r];
#pragma unroll
        for (int c2 = 0; c2 < CK / 2; c2++) {
            float2 qi = q2[c2];
            dot0 = fmaf(qi.x, qj[2 * c2], dot0);
            dot1 = fmaf(qi.y, qj[2 * c2 + 1], dot1);
        }
        float ss = fmaxf(fmaf(dot0 + dot1, -2.0f, sSi[r] + Sj), 0.0f);
        float Dv = (i == j) ? FLT_MAX : fmaf(ss, djsq, 1e-10f);
        D[r] = Dv;

        // Independent of the dot: gumbel ratio for this (b,i,j)
        uint32_t e = 2u * ((((uint32_t)b << 18)) + ((uint32_t)i << 9) + (uint32_t)j);
        float u0 = jax_uniform(jax_bits(e,      one));
        float u1 = jax_uniform(jax_bits(e + 1u, one));
        float L0 = -__log2f(u0);
        float L1 = -__log2f(u1);
        sT[r][j] = __fdividef(L1, L0);

        // Per-warp running row min
        float v = Dv;
#pragma unroll
        for (int o = 16; o; o >>= 1)
            v = fminf(v, __shfl_xor_sync(0xffffffffu, v, o));
        if (lane == 0) sRed[wid][r] = v;
    }
    __syncthreads();

    // Phase B: warp w (w<8) combines 16 warp-partials of row w.
    if (wid < ROWS) {
        float v = (lane < 16) ? sRed[lane][wid] : FLT_MAX;
#pragma unroll
        for (int o = 8; o; o >>= 1)
            v = fminf(v, __shfl_xor_sync(0xffffffffu, v, o));
        if (lane == 0) sA[wid] = 0.99f * v;
    }
    __syncthreads();

    // Phase C: decisions -> ballot bitmasks (1 STG.32 per warp-row).
    // decide a^2*L1 >= bb^2*L0  <=>  a^2*t >= bb^2,  t = L1/L0.
#pragma unroll
    for (int r = 0; r < ROWS; r++) {
        const int i = i0 + r;
        const bool diag = (i == j);
        float ar = sA[r];
        float a  = diag ? 0.99f : ar;
        float bb = diag ? 0.01f : D[r] - ar;
        float t  = sT[r][j];

        uint32_t m = __ballot_sync(0xffffffffu, a * a * t >= bb * bb);
        if (lane == 0)
            g_mask[(((uint32_t)(b * KK + i)) << 4) + (uint32_t)wid] = m;
    }
}

// ---------------------------------------------------------------------------
// Pack kernel: out[i][j] = 0.125 * sum_b bit(b,i,j). Word loads are warp-
// broadcast (32 consecutive j share one mask word).
// ---------------------------------------------------------------------------
__global__ void __launch_bounds__(256)
pack_kernel(float* __restrict__ out) {
    const uint32_t t = blockIdx.x * 256u + threadIdx.x;    // (i<<9) + j
    const uint32_t w = t >> 5;                             // (i<<4) + (j>>5)
    const int bit = (int)(t & 31u);

    int acc = 0;
#pragma unroll
    for (int b = 0; b < BK; b++)
        acc += (int)((g_mask[((uint32_t)b << 13) + w] >> bit) & 1u);

    out[t] = 0.125f * (float)acc;
}

// ---------------------------------------------------------------------------
// Launch
// ---------------------------------------------------------------------------
extern "C" void kernel_launch(void* const* d_in, const int* in_sizes, int n_in,
                              void* d_out, int out_size) {
    const float* amp = (const float*)d_in[0];
    const float* ph  = (const float*)d_in[1];
    const float* A   = (const float*)d_in[2];
    const float* wa  = (const float*)d_in[3];
    const float* wp  = (const float*)d_in[4];
    float* out = (float*)d_out;

    fused_kernel<<<dim3(KK / ROWS, BK), TPB>>>(amp, ph, A, wa, wp, 1u);
    pack_kernel<<<(KK * KK) / 256, 256>>>(out);
}

// round 14
// speedup vs baseline: 1.0199x; 1.0199x over previous
#include <cuda_runtime.h>
#include <cstdint>
#include <math.h>
#include <float.h>

// Problem constants
#define BK  8
#define CK  32
#define KK  512
#define ROWS 8
#define TPB 512

// Decision bitmasks: bit (j&31) of g_mask[(b<<13) + (i<<4) + (j>>5)]  (256 KB)
#define MASK_WORDS_PER_B (KK * (KK / 32))   // 8192
__device__ uint32_t g_mask[BK * MASK_WORDS_PER_B];

// ---------------------------------------------------------------------------
// JAX threefry2x32, key = (0, 42).  Random123 Threefry-2x32-20.
// Adds (round + key injection) issued as IMAD via opaque `one` (fma pipe);
// rotations single SHF via __funnelshift_l; xors LOP3. 3 ops per round.
// ---------------------------------------------------------------------------
#define MAD(dst, addend) \
    asm("mad.lo.s32 %0, %1, %2, %0;" : "+r"(dst) : "r"(addend), "r"(one))
#define MADC(dst, cst) { uint32_t k_ = (cst); MAD(dst, k_); }
#define TF_R(r) { MAD(x0, x1); x1 = __funnelshift_l(x1, x1, (r)); x1 ^= x0; }

__device__ __forceinline__ uint32_t jax_bits(uint32_t e, uint32_t one) {
    uint32_t x0 = 0u, x1 = e;
    const uint32_t ks1 = 42u;
    const uint32_t ks2 = 0x1BD11BDAu ^ 42u;
    /* x0 += 0 */  MADC(x1, ks1);
    TF_R(13) TF_R(15) TF_R(26) TF_R(6)
    MADC(x0, ks1); MADC(x1, ks2 + 1u);
    TF_R(17) TF_R(29) TF_R(16) TF_R(24)
    MADC(x0, ks2); MADC(x1, 2u);
    TF_R(13) TF_R(15) TF_R(26) TF_R(6)
    /* x0 += 0 */  MADC(x1, ks1 + 3u);
    TF_R(17) TF_R(29) TF_R(16) TF_R(24)
    MADC(x0, ks1); MADC(x1, ks2 + 4u);
    TF_R(13) TF_R(15) TF_R(26) TF_R(6)
    MADC(x0, ks2); MADC(x1, 5u);
    return x0 ^ x1;
}

// jax.random.uniform bit->float, minval=1e-10, maxval=1.0 (f32).
// f in [0,1) so max(1e-10, f+1e-10) == f+1e-10 exactly.
__device__ __forceinline__ float jax_uniform(uint32_t bits) {
    float f = __uint_as_float((bits >> 9) | 0x3f800000u) - 1.0f;
    return f + 1e-10f;
}

// ---------------------------------------------------------------------------
// Fused kernel (R10 phase structure): distances (regs) + smem-transpose row
// min + gumbel-bernoulli decisions, emitted as ballot bitmasks.
// Block = (8-row i-tile, batch b), thread = column j.
// ---------------------------------------------------------------------------
__global__ void __launch_bounds__(TPB, 2)
fused_kernel(const float* __restrict__ amp,
             const float* __restrict__ ph,
             const float* __restrict__ Amat,
             const float* __restrict__ wamp_p,
             const float* __restrict__ wph_p,
             uint32_t one) {
    __shared__ float sQi[ROWS][CK];      // row vectors q_i
    __shared__ float sSi[ROWS];          // ||q_i||^2
    __shared__ float sD[ROWS][KK];       // D tile for min reduction (16 KB)
    __shared__ float sA[ROWS];           // 0.99 * Dmin per row

    const int b    = blockIdx.y;
    const int j    = threadIdx.x;
    const int wid  = j >> 5;
    const int lane = j & 31;
    const int i0   = blockIdx.x * ROWS;

    const float wa = wamp_p[0];
    const float wp = wph_p[0];

    const float* ab = amp + (size_t)b * CK * KK;
    const float* pb = ph  + (size_t)b * CK * KK;

    // Per-thread column cache q_j[c] and its sum of squares
    float qj[CK];
    float Sj = 0.0f;
#pragma unroll
    for (int c = 0; c < CK; c++) {
        float v = wa * ab[c * KK + j] + wp * pb[c * KK + j];
        qj[c] = v;
        Sj = fmaf(v, v, Sj);
    }

    // Warps 0..7 load the 8 row vectors (lane = channel) + row SSQ
    if (wid < ROWS) {
        const int i = i0 + wid;
        float v = wa * ab[lane * KK + i] + wp * pb[lane * KK + i];
        sQi[wid][lane] = v;
        float s = v * v;
#pragma unroll
        for (int o = 16; o; o >>= 1)
            s += __shfl_xor_sync(0xffffffffu, s, o);
        if (lane == 0) sSi[wid] = s;
    }

    const float dj   = Amat[(size_t)j * KK + j];
    const float djsq = dj * dj;
    __syncthreads();

    // Phase A: D = djsq * ||q_i - q_j||^2 + 1e-10 (expanded dot).
    float D[ROWS];
#pragma unroll
    for (int r = 0; r < ROWS; r++) {
        float dot = 0.0f;
        const float2* q2 = (const float2*)sQi[r];
#pragma unroll
        for (int c2 = 0; c2 < CK / 2; c2++) {
            float2 qi = q2[c2];
            dot = fmaf(qi.x, qj[2 * c2], dot);
            dot = fmaf(qi.y, qj[2 * c2 + 1], dot);
        }
        float ss = fmaxf(fmaf(dot, -2.0f, sSi[r] + Sj), 0.0f);
        const int i = i0 + r;
        float Dv = (i == j) ? FLT_MAX : fmaf(ss, djsq, 1e-10f);
        D[r] = Dv;
        sD[r][j] = Dv;
    }
    __syncthreads();

    // Phase B: warp w (w<8) min-reduces row w (strided LDS + shuffle tree).
    if (wid < ROWS) {
        float v = FLT_MAX;
#pragma unroll
        for (int k = 0; k < KK / 32; k++)
            v = fminf(v, sD[wid][lane + 32 * k]);
#pragma unroll
        for (int o = 16; o; o >>= 1)
            v = fminf(v, __shfl_xor_sync(0xffffffffu, v, o));
        if (lane == 0) sA[wid] = 0.99f * v;
    }
    __syncthreads();

    // Phase C: gumbel-bernoulli decisions -> ballot bitmask (1 STG.32/warp-row)
    // decide logit+g0 >= -logit+g1  <=>  a^2*L1 >= bb^2*L0 (log base cancels)
#pragma unroll
    for (int r = 0; r < ROWS; r++) {
        const int i = i0 + r;
        const bool diag = (i == j);
        float ar = sA[r];
        float a  = diag ? 0.99f : ar;
        float bb = diag ? 0.01f : D[r] - ar;

        uint32_t e = 2u * ((((uint32_t)b << 18)) + ((uint32_t)i << 9) + (uint32_t)j);
        float u0 = jax_uniform(jax_bits(e,      one));
        float u1 = jax_uniform(jax_bits(e + 1u, one));
        float L0 = -__log2f(u0);
        float L1 = -__log2f(u1);

        uint32_t m = __ballot_sync(0xffffffffu, a * a * L1 >= bb * bb * L0);
        if (lane == 0)
            g_mask[((uint32_t)b << 13) + ((uint32_t)i << 4) + (uint32_t)wid] = m;
    }
}

// ---------------------------------------------------------------------------
// Pack kernel: out[i][j] = 0.125 * sum_b bit(b,i,j).
// A warp covers 32 consecutive elements sharing ONE mask-word index w:
// lanes 0..7 load the 8 per-batch words in a single coalesced LDG warp-op,
// __shfl_sync broadcasts, each lane extracts its bit. 8K LDG warp-ops total.
// ---------------------------------------------------------------------------
__global__ void __launch_bounds__(256)
pack_kernel(float* __restrict__ out) {
    const uint32_t t = blockIdx.x * 256u + threadIdx.x;    // (i<<9) + j
    const int lane = (int)(t & 31u);
    const uint32_t w = t >> 5;                             // shared by the warp

    uint32_t wv = 0;
    if (lane < BK)
        wv = g_mask[((uint32_t)lane << 13) + w];

    int acc = 0;
#pragma unroll
    for (int b = 0; b < BK; b++) {
        uint32_t word = __shfl_sync(0xffffffffu, wv, b);
        acc += (int)((word >> lane) & 1u);
    }
    out[t] = 0.125f * (float)acc;
}

// ---------------------------------------------------------------------------
// Launch
// ---------------------------------------------------------------------------
extern "C" void kernel_launch(void* const* d_in, const int* in_sizes, int n_in,
                              void* d_out, int out_size) {
    const float* amp = (const float*)d_in[0];
    const float* ph  = (const float*)d_in[1];
    const float* A   = (const float*)d_in[2];
    const float* wa  = (const float*)d_in[3];
    const float* wp  = (const float*)d_in[4];
    float* out = (float*)d_out;

    fused_kernel<<<dim3(KK / ROWS, BK), TPB>>>(amp, ph, A, wa, wp, 1u);
    pack_kernel<<<(KK * KK) / 256, 256>>>(out);
}

// round 15
// speedup vs baseline: 1.1336x; 1.1115x over previous
#include <cuda_runtime.h>
#include <cstdint>
#include <math.h>
#include <float.h>

// Problem constants
#define BK  8
#define CK  32
#define KK  512
#define ROWS 16
#define TPB 512

// Scratch: raw D per (b,i,j); a = 0.99*Dmin per (b,i)
__device__ float g_D[BK * KK * KK];    // 8 MB
__device__ float g_a[BK * KK];         // 16 KB

// ---------------------------------------------------------------------------
// JAX threefry2x32, key = (0, 42).  Random123 Threefry-2x32-20.
// Adds (round + key injection) issued as IMAD via opaque `one` (fma pipe);
// rotations single SHF via __funnelshift_l; xors LOP3. 3 ops per round.
// ---------------------------------------------------------------------------
#define MAD(dst, addend) \
    asm("mad.lo.s32 %0, %1, %2, %0;" : "+r"(dst) : "r"(addend), "r"(one))
#define MADC(dst, cst) { uint32_t k_ = (cst); MAD(dst, k_); }
#define TF_R(r) { MAD(x0, x1); x1 = __funnelshift_l(x1, x1, (r)); x1 ^= x0; }

__device__ __forceinline__ uint32_t jax_bits(uint32_t e, uint32_t one) {
    uint32_t x0 = 0u, x1 = e;
    const uint32_t ks1 = 42u;
    const uint32_t ks2 = 0x1BD11BDAu ^ 42u;
    /* x0 += 0 */  MADC(x1, ks1);
    TF_R(13) TF_R(15) TF_R(26) TF_R(6)
    MADC(x0, ks1); MADC(x1, ks2 + 1u);
    TF_R(17) TF_R(29) TF_R(16) TF_R(24)
    MADC(x0, ks2); MADC(x1, 2u);
    TF_R(13) TF_R(15) TF_R(26) TF_R(6)
    /* x0 += 0 */  MADC(x1, ks1 + 3u);
    TF_R(17) TF_R(29) TF_R(16) TF_R(24)
    MADC(x0, ks1); MADC(x1, ks2 + 4u);
    TF_R(13) TF_R(15) TF_R(26) TF_R(6)
    MADC(x0, ks2); MADC(x1, 5u);
    return x0 ^ x1;
}

// jax.random.uniform bit->float, minval=1e-10, maxval=1.0 (f32).
// f in [0,1) so max(1e-10, f+1e-10) == f+1e-10 exactly.
__device__ __forceinline__ float jax_uniform(uint32_t bits) {
    float f = __uint_as_float((bits >> 9) | 0x3f800000u) - 1.0f;
    return f + 1e-10f;
}

// ---------------------------------------------------------------------------
// Kernel 1: distances + row minima  ->  g_D (raw), g_a (0.99*Dmin)
// 256 blocks (single wave at 2 CTA/SM), 16 rows per block.
// Row minima via smem transpose (phase B gives each warp one full row).
// ---------------------------------------------------------------------------
__global__ void __launch_bounds__(TPB, 2)
dist_kernel(const float* __restrict__ amp,
            const float* __restrict__ ph,
            const float* __restrict__ Amat,
            const float* __restrict__ wamp_p,
            const float* __restrict__ wph_p) {
    __shared__ float sQi[ROWS][CK];      // row vectors q_i
    __shared__ float sSi[ROWS];          // ||q_i||^2
    __shared__ float sD[ROWS][KK];       // D tile for min reduction (32 KB)

    const int b    = blockIdx.y;
    const int j    = threadIdx.x;
    const int wid  = j >> 5;
    const int lane = j & 31;
    const int i0   = blockIdx.x * ROWS;

    const float wa = wamp_p[0];
    const float wp = wph_p[0];

    const float* ab = amp + (size_t)b * CK * KK;
    const float* pb = ph  + (size_t)b * CK * KK;

    // Per-thread column cache q_j[c] and its sum of squares
    float qj[CK];
    float Sj = 0.0f;
#pragma unroll
    for (int c = 0; c < CK; c++) {
        float v = wa * ab[c * KK + j] + wp * pb[c * KK + j];
        qj[c] = v;
        Sj = fmaf(v, v, Sj);
    }

    // Each of the 16 warps loads its row vector (lane = channel) + row SSQ
    {
        const int i = i0 + wid;
        float v = wa * ab[lane * KK + i] + wp * pb[lane * KK + i];
        sQi[wid][lane] = v;
        float s = v * v;
#pragma unroll
        for (int o = 16; o; o >>= 1)
            s += __shfl_xor_sync(0xffffffffu, s, o);
        if (lane == 0) sSi[wid] = s;
    }

    const float dj   = Amat[(size_t)j * KK + j];
    const float djsq = dj * dj;
    __syncthreads();

    // Phase A: D = djsq * ||q_i - q_j||^2 + 1e-10 (expanded dot); store only.
#pragma unroll
    for (int r = 0; r < ROWS; r++) {
        float dot = 0.0f;
        const float2* q2 = (const float2*)sQi[r];
#pragma unroll
        for (int c2 = 0; c2 < CK / 2; c2++) {
            float2 qi = q2[c2];
            dot = fmaf(qi.x, qj[2 * c2], dot);
            dot = fmaf(qi.y, qj[2 * c2 + 1], dot);
        }
        float ss = fmaxf(fmaf(dot, -2.0f, sSi[r] + Sj), 0.0f);
        const int i = i0 + r;
        float D = (i == j) ? FLT_MAX : fmaf(ss, djsq, 1e-10f);
        g_D[((uint32_t)(b * KK + i) << 9) + (uint32_t)j] = D;
        sD[r][j] = D;
    }
    __syncthreads();

    // Phase B: warp w min-reduces row w (strided LDS + warp shuffle tree).
    {
        float v = FLT_MAX;
#pragma unroll
        for (int k = 0; k < KK / 32; k++)
            v = fminf(v, sD[wid][lane + 32 * k]);
#pragma unroll
        for (int o = 16; o; o >>= 1)
            v = fminf(v, __shfl_xor_sync(0xffffffffu, v, o));
        if (lane == 0) g_a[b * KK + i0 + wid] = 0.99f * v;
    }
}

// ---------------------------------------------------------------------------
// Kernel 2: gumbel-bernoulli decisions + mean over b  ->  out
// Each thread handles TWO same-row elements (j, j+256): 4 independent
// threefry chains per b-iteration (ILP 4) and one shared row-min load.
// Block 256, grid 512, <=64 regs -> 4 CTAs/SM cap, 592 slots >= 512 CTAs
// -> single wave.
// ---------------------------------------------------------------------------
__global__ void __launch_bounds__(256, 4)
sample_kernel(float* __restrict__ out, uint32_t one) {
    const uint32_t t   = blockIdx.x * 256u + threadIdx.x;  // 0..131071
    const uint32_t i   = t >> 8;                           // output row
    const uint32_t jlo = t & 255u;                         // first column
    const uint32_t m0  = (i << 9) + jlo;                   // element (i, jlo)

    const bool dg0 = (jlo == i);            // (i, jlo) on diagonal (i < 256)
    const bool dg1 = (jlo + 256u == i);     // (i, jlo+256) on diagonal

    const float* __restrict__ Dp = g_D + m0;
    const float* __restrict__ ap = g_a + i;

    float c0 = 0.0f, c1 = 0.0f;
#pragma unroll
    for (int b = 0; b < BK; b++) {
        const uint32_t boff = (uint32_t)b << 18;
        float D0 = Dp[boff];
        float D1 = Dp[boff + 256u];
        float ar = ap[b << 9];

        uint32_t e = 2u * (boff + m0);
        // four independent threefry chains
        float u0 = jax_uniform(jax_bits(e,        one));
        float u1 = jax_uniform(jax_bits(e + 1u,   one));
        float u2 = jax_uniform(jax_bits(e + 512u, one));
        float u3 = jax_uniform(jax_bits(e + 513u, one));
        float L0 = -__log2f(u0);
        float L1 = -__log2f(u1);
        float L2 = -__log2f(u2);
        float L3 = -__log2f(u3);

        float a0 = dg0 ? 0.99f : ar, b0 = dg0 ? 0.01f : D0 - ar;
        float a1 = dg1 ? 0.99f : ar, b1 = dg1 ? 0.01f : D1 - ar;

        c0 += (a0 * a0 * L1 >= b0 * b0 * L0) ? 0.125f : 0.0f;
        c1 += (a1 * a1 * L3 >= b1 * b1 * L2) ? 0.125f : 0.0f;
    }
    out[m0]        = c0;
    out[m0 + 256u] = c1;
}

// ---------------------------------------------------------------------------
// Launch
// ---------------------------------------------------------------------------
extern "C" void kernel_launch(void* const* d_in, const int* in_sizes, int n_in,
                              void* d_out, int out_size) {
    const float* amp = (const float*)d_in[0];
    const float* ph  = (const float*)d_in[1];
    const float* A   = (const float*)d_in[2];
    const float* wa  = (const float*)d_in[3];
    const float* wp  = (const float*)d_in[4];
    float* out = (float*)d_out;

    dist_kernel<<<dim3(KK / ROWS, BK), TPB>>>(amp, ph, A, wa, wp);
    sample_kernel<<<(KK * KK) / 512, 256>>>(out, 1u);
}